// round 1
// baseline (speedup 1.0000x reference)
#include <cuda_runtime.h>
#include <cuda_bf16.h>
#include <math.h>

#define S_LEN 4096
#define D_DIM 2048
#define NHEAD 16
#define HD    128

// Scratch (allocation-free): q/k/v in [H, S, hd], attention output in [S, D]
__device__ float g_q[NHEAD * S_LEN * HD];
__device__ float g_k[NHEAD * S_LEN * HD];
__device__ float g_v[NHEAD * S_LEN * HD];
__device__ float g_att[S_LEN * D_DIM];

// ---------------------------------------------------------------------------
// 128x128x8 register-blocked SGEMM, 256 threads, 8x8 microtile per thread.
// MODE 0: C[m*N+n] plain row-major
// MODE 1: scatter columns into [head, m, d] layout (head = n>>7, d = n&127)
// ---------------------------------------------------------------------------
template <int MODE>
__global__ __launch_bounds__(256, 2)
void sgemm128(const float* __restrict__ A, const float* __restrict__ B,
              float* __restrict__ C, int M, int N, int K)
{
    __shared__ float As[8][128];   // As[k][m] (transposed A tile)
    __shared__ float Bs[8][128];   // Bs[k][n]

    const int bm = blockIdx.y * 128;
    const int bn = blockIdx.x * 128;
    const int t  = threadIdx.x;
    const int tx = t & 15;         // 16 cols of microtiles
    const int ty = t >> 4;         // 16 rows of microtiles

    // A tile load: 128 rows x 8 cols; thread -> row t>>1, 4 consecutive k
    const int ar  = t >> 1;
    const int ac4 = (t & 1) * 4;
    // B tile load: 8 rows x 128 cols; thread -> row t>>5, 4 consecutive n
    const int br  = t >> 5;
    const int bc4 = (t & 31) * 4;

    const float* Ap = A + (long)(bm + ar) * K + ac4;
    const float* Bp = B + (long)br * N + bn + bc4;

    float acc[8][8];
#pragma unroll
    for (int i = 0; i < 8; i++)
#pragma unroll
        for (int j = 0; j < 8; j++) acc[i][j] = 0.0f;

    for (int k0 = 0; k0 < K; k0 += 8) {
        float4 av = *(const float4*)Ap;
        float4 bv = *(const float4*)Bp;
        As[ac4 + 0][ar] = av.x;
        As[ac4 + 1][ar] = av.y;
        As[ac4 + 2][ar] = av.z;
        As[ac4 + 3][ar] = av.w;
        *(float4*)&Bs[br][bc4] = bv;
        __syncthreads();

#pragma unroll
        for (int k = 0; k < 8; k++) {
            float a[8], b[8];
            *(float4*)&a[0] = *(const float4*)&As[k][ty * 8];
            *(float4*)&a[4] = *(const float4*)&As[k][ty * 8 + 4];
            *(float4*)&b[0] = *(const float4*)&Bs[k][tx * 8];
            *(float4*)&b[4] = *(const float4*)&Bs[k][tx * 8 + 4];
#pragma unroll
            for (int i = 0; i < 8; i++)
#pragma unroll
                for (int j = 0; j < 8; j++)
                    acc[i][j] = fmaf(a[i], b[j], acc[i][j]);
        }
        __syncthreads();
        Ap += 8;
        Bp += (long)8 * N;
    }

#pragma unroll
    for (int i = 0; i < 8; i++) {
        const int m = bm + ty * 8 + i;
#pragma unroll
        for (int j = 0; j < 8; j++) {
            const int n = bn + tx * 8 + j;
            if (MODE == 0) {
                C[(long)m * N + n] = acc[i][j];
            } else {
                // [head, m, d] layout for attention consumption
                C[(long)(n >> 7) * (S_LEN * HD) + (long)m * HD + (n & 127)] = acc[i][j];
            }
        }
    }
}

// ---------------------------------------------------------------------------
// Flash attention (fp32, causal). One CTA per (q-block of 64 rows, head).
// 256 threads: 16x16 layout. QK^T: 4x4 scores/thread. PV: 4 rows x 8 cols.
// Online softmax; O, m, l register-resident.
// ---------------------------------------------------------------------------
__global__ __launch_bounds__(256, 1)
void attn_fwd(const float* __restrict__ gq, const float* __restrict__ gk,
              const float* __restrict__ gv, float* __restrict__ gout)
{
    extern __shared__ float sm[];
    float* Qt = sm;                    // [128][65]  Qt[d][m]
    float* Kt = Qt + 128 * 65;         // [128][65]  Kt[d][n]
    float* Vs = Kt + 128 * 65;         // [64][128]  Vs[kv][d]
    float* Ss = Vs + 64 * 128;         // [64][65]   probabilities

    const int qb = blockIdx.x;         // 0..63 (64-row q block)
    const int h  = blockIdx.y;         // head
    const int t  = threadIdx.x;
    const int tx = t & 15;
    const int ty = t >> 4;
    const int r0 = ty * 4;             // this thread's 4 q-rows
    const int c0 = tx * 4;             // this thread's 4 k-cols (QK phase)

    const float scale = 0.08838834764831845f;  // 1/sqrt(128)

    // Load Q block transposed into smem (coalesced gmem, stride-65 smem)
    const float* qbase = gq + (long)h * S_LEN * HD + (long)qb * 64 * HD;
#pragma unroll
    for (int rep = 0; rep < 32; rep++) {
        int idx = t + rep * 256;       // idx = row*128 + d
        int row = idx >> 7, d = idx & 127;
        Qt[d * 65 + row] = qbase[idx];
    }

    float mI[4], lI[4], O[4][8];
#pragma unroll
    for (int i = 0; i < 4; i++) {
        mI[i] = -1e30f; lI[i] = 0.0f;
#pragma unroll
        for (int j = 0; j < 8; j++) O[i][j] = 0.0f;
    }

    for (int jb = 0; jb <= qb; jb++) {
        const float* kbase = gk + (long)h * S_LEN * HD + (long)jb * 64 * HD;
        const float* vbase = gv + (long)h * S_LEN * HD + (long)jb * 64 * HD;
#pragma unroll
        for (int rep = 0; rep < 32; rep++) {
            int idx = t + rep * 256;
            int row = idx >> 7, d = idx & 127;
            Kt[d * 65 + row] = kbase[idx];
            Vs[idx]          = vbase[idx];
        }
        __syncthreads();

        // ---- S = Q K^T (4x4 per thread) ----
        float sc[4][4];
#pragma unroll
        for (int i = 0; i < 4; i++)
#pragma unroll
            for (int j = 0; j < 4; j++) sc[i][j] = 0.0f;

#pragma unroll 8
        for (int d = 0; d < 128; d++) {
            float a0 = Qt[d * 65 + r0 + 0];
            float a1 = Qt[d * 65 + r0 + 1];
            float a2 = Qt[d * 65 + r0 + 2];
            float a3 = Qt[d * 65 + r0 + 3];
            float b0 = Kt[d * 65 + c0 + 0];
            float b1 = Kt[d * 65 + c0 + 1];
            float b2 = Kt[d * 65 + c0 + 2];
            float b3 = Kt[d * 65 + c0 + 3];
            sc[0][0] = fmaf(a0, b0, sc[0][0]); sc[0][1] = fmaf(a0, b1, sc[0][1]);
            sc[0][2] = fmaf(a0, b2, sc[0][2]); sc[0][3] = fmaf(a0, b3, sc[0][3]);
            sc[1][0] = fmaf(a1, b0, sc[1][0]); sc[1][1] = fmaf(a1, b1, sc[1][1]);
            sc[1][2] = fmaf(a1, b2, sc[1][2]); sc[1][3] = fmaf(a1, b3, sc[1][3]);
            sc[2][0] = fmaf(a2, b0, sc[2][0]); sc[2][1] = fmaf(a2, b1, sc[2][1]);
            sc[2][2] = fmaf(a2, b2, sc[2][2]); sc[2][3] = fmaf(a2, b3, sc[2][3]);
            sc[3][0] = fmaf(a3, b0, sc[3][0]); sc[3][1] = fmaf(a3, b1, sc[3][1]);
            sc[3][2] = fmaf(a3, b2, sc[3][2]); sc[3][3] = fmaf(a3, b3, sc[3][3]);
        }

        // scale + causal mask (only the diagonal block needs masking)
        if (jb == qb) {
#pragma unroll
            for (int i = 0; i < 4; i++)
#pragma unroll
                for (int j = 0; j < 4; j++) {
                    float v = sc[i][j] * scale;
                    sc[i][j] = ((c0 + j) > (r0 + i)) ? -1e30f : v;
                }
        } else {
#pragma unroll
            for (int i = 0; i < 4; i++)
#pragma unroll
                for (int j = 0; j < 4; j++) sc[i][j] *= scale;
        }

        // ---- online softmax ----
        float rmax[4];
#pragma unroll
        for (int i = 0; i < 4; i++)
            rmax[i] = fmaxf(fmaxf(sc[i][0], sc[i][1]), fmaxf(sc[i][2], sc[i][3]));
#pragma unroll
        for (int off = 1; off < 16; off <<= 1)
#pragma unroll
            for (int i = 0; i < 4; i++)
                rmax[i] = fmaxf(rmax[i], __shfl_xor_sync(0xffffffffu, rmax[i], off));

        float alpha[4], rsum[4];
#pragma unroll
        for (int i = 0; i < 4; i++) {
            float nm = fmaxf(mI[i], rmax[i]);
            alpha[i] = __expf(mI[i] - nm);
            mI[i] = nm;
            float s = 0.0f;
#pragma unroll
            for (int j = 0; j < 4; j++) {
                float p = __expf(sc[i][j] - nm);
                Ss[(r0 + i) * 65 + c0 + j] = p;
                s += p;
            }
            rsum[i] = s;
        }
#pragma unroll
        for (int off = 1; off < 16; off <<= 1)
#pragma unroll
            for (int i = 0; i < 4; i++)
                rsum[i] += __shfl_xor_sync(0xffffffffu, rsum[i], off);
#pragma unroll
        for (int i = 0; i < 4; i++) {
            lI[i] = lI[i] * alpha[i] + rsum[i];
#pragma unroll
            for (int j = 0; j < 8; j++) O[i][j] *= alpha[i];
        }
        __syncthreads();

        // ---- O += P V  (4 rows x 8 cols/thread; col c = tx + 16*j) ----
#pragma unroll 4
        for (int kk = 0; kk < 64; kk++) {
            float sv0 = Ss[(r0 + 0) * 65 + kk];
            float sv1 = Ss[(r0 + 1) * 65 + kk];
            float sv2 = Ss[(r0 + 2) * 65 + kk];
            float sv3 = Ss[(r0 + 3) * 65 + kk];
            float vv[8];
#pragma unroll
            for (int j = 0; j < 8; j++) vv[j] = Vs[kk * 128 + tx + 16 * j];
#pragma unroll
            for (int j = 0; j < 8; j++) {
                O[0][j] = fmaf(sv0, vv[j], O[0][j]);
                O[1][j] = fmaf(sv1, vv[j], O[1][j]);
                O[2][j] = fmaf(sv2, vv[j], O[2][j]);
                O[3][j] = fmaf(sv3, vv[j], O[3][j]);
            }
        }
        __syncthreads();
    }

    // epilogue: normalize, write attention output in [S, D] layout
#pragma unroll
    for (int i = 0; i < 4; i++) {
        float inv = 1.0f / lI[i];
        int srow = qb * 64 + r0 + i;
#pragma unroll
        for (int j = 0; j < 8; j++) {
            gout[(long)srow * D_DIM + h * HD + tx + 16 * j] = O[i][j] * inv;
        }
    }
}

// ---------------------------------------------------------------------------
extern "C" void kernel_launch(void* const* d_in, const int* in_sizes, int n_in,
                              void* d_out, int out_size)
{
    const float* hs = (const float*)d_in[0];
    const float* Wq = (const float*)d_in[1];
    const float* Wk = (const float*)d_in[2];
    const float* Wv = (const float*)d_in[3];
    const float* Wo = (const float*)d_in[4];
    float* out = (float*)d_out;

    float *q, *k, *v, *att;
    cudaGetSymbolAddress((void**)&q,   g_q);
    cudaGetSymbolAddress((void**)&k,   g_k);
    cudaGetSymbolAddress((void**)&v,   g_v);
    cudaGetSymbolAddress((void**)&att, g_att);

    dim3 gg(D_DIM / 128, S_LEN / 128);   // (16, 32)

    sgemm128<1><<<gg, 256>>>(hs, Wq, q, S_LEN, D_DIM, D_DIM);
    sgemm128<1><<<gg, 256>>>(hs, Wk, k, S_LEN, D_DIM, D_DIM);
    sgemm128<1><<<gg, 256>>>(hs, Wv, v, S_LEN, D_DIM, D_DIM);

    const int smem = (128 * 65 * 2 + 64 * 128 + 64 * 65) * (int)sizeof(float);
    cudaFuncSetAttribute(attn_fwd, cudaFuncAttributeMaxDynamicSharedMemorySize, smem);
    attn_fwd<<<dim3(S_LEN / 64, NHEAD), 256, smem>>>(q, k, v, att);

    sgemm128<0><<<gg, 256>>>(att, Wo, out, S_LEN, D_DIM, D_DIM);
}

// round 3
// speedup vs baseline: 1.5962x; 1.5962x over previous
#include <cuda_runtime.h>
#include <cuda_bf16.h>
#include <math.h>
#include <cstdint>

#define S_LEN 4096
#define D_DIM 2048
#define NHEAD 16
#define HD    128

// ---------------- scratch (allocation-free) ----------------
__device__ float g_q[NHEAD * S_LEN * HD];
__device__ float g_k[NHEAD * S_LEN * HD];
__device__ float g_v[NHEAD * S_LEN * HD];
__device__ float g_att[S_LEN * D_DIM];

__device__ __nv_bfloat16 g_hs_h[S_LEN * D_DIM];
__device__ __nv_bfloat16 g_hs_l[S_LEN * D_DIM];
__device__ __nv_bfloat16 g_w_h[4][D_DIM * D_DIM];   // transposed: [N][K]
__device__ __nv_bfloat16 g_w_l[4][D_DIM * D_DIM];
__device__ __nv_bfloat16 g_att_h[S_LEN * D_DIM];
__device__ __nv_bfloat16 g_att_l[S_LEN * D_DIM];

// ---------------- helpers ----------------
__device__ __forceinline__ uint32_t smem_u32(const void* p) {
    uint32_t a;
    asm("{ .reg .u64 t; cvta.to.shared.u64 t, %1; cvt.u32.u64 %0, t; }" : "=r"(a) : "l"(p));
    return a;
}

__device__ __forceinline__ void ldm_x4(uint32_t& r0, uint32_t& r1, uint32_t& r2, uint32_t& r3,
                                       uint32_t addr) {
    asm volatile("ldmatrix.sync.aligned.m8n8.x4.shared.b16 {%0,%1,%2,%3}, [%4];"
                 : "=r"(r0), "=r"(r1), "=r"(r2), "=r"(r3) : "r"(addr));
}

__device__ __forceinline__ void mma16816(float* c, const uint32_t* a, const uint32_t* b) {
    asm volatile(
        "mma.sync.aligned.m16n8k16.row.col.f32.bf16.bf16.f32 "
        "{%0,%1,%2,%3}, {%4,%5,%6,%7}, {%8,%9}, {%0,%1,%2,%3};"
        : "+f"(c[0]), "+f"(c[1]), "+f"(c[2]), "+f"(c[3])
        : "r"(a[0]), "r"(a[1]), "r"(a[2]), "r"(a[3]), "r"(b[0]), "r"(b[1]));
}

__device__ __forceinline__ void cp_async16(uint32_t s, const void* g) {
    asm volatile("cp.async.cg.shared.global [%0], [%1], 16;" :: "r"(s), "l"(g));
}

// swizzle for 64-byte rows (32 bf16): XOR chunk column by row bits
#define SWZ64(o) ((o) ^ (((o) >> 3) & 0x30))

// ---------------------------------------------------------------------------
// Split kernels: fp32 -> (hi, lo) bf16, hi + lo ~= x (residual ~2^-18)
// ---------------------------------------------------------------------------
__global__ void split_kernel(const float* __restrict__ in,
                             __nv_bfloat16* __restrict__ hi,
                             __nv_bfloat16* __restrict__ lo, int n2)
{
    int i = blockIdx.x * blockDim.x + threadIdx.x;
    int stride = gridDim.x * blockDim.x;
    for (; i < n2; i += stride) {
        float2 x = ((const float2*)in)[i];
        __nv_bfloat16 h0 = __float2bfloat16(x.x);
        __nv_bfloat16 h1 = __float2bfloat16(x.y);
        __nv_bfloat16 l0 = __float2bfloat16(x.x - __bfloat162float(h0));
        __nv_bfloat16 l1 = __float2bfloat16(x.y - __bfloat162float(h1));
        ((__nv_bfloat162*)hi)[i] = __nv_bfloat162(h0, h1);
        ((__nv_bfloat162*)lo)[i] = __nv_bfloat162(l0, l1);
    }
}

// Transpose + split: W [K, N] fp32 -> Wt_hi/lo [N, K] bf16
__global__ void splitT_kernel(const float* __restrict__ W,
                              __nv_bfloat16* __restrict__ th,
                              __nv_bfloat16* __restrict__ tl)
{
    __shared__ float tile[32][33];
    const int n0 = blockIdx.x * 32;
    const int k0 = blockIdx.y * 32;
    const int tx = threadIdx.x, ty = threadIdx.y;   // (32, 8)
#pragma unroll
    for (int i = 0; i < 4; i++)
        tile[ty + i * 8][tx] = W[(long)(k0 + ty + i * 8) * D_DIM + n0 + tx];
    __syncthreads();
#pragma unroll
    for (int i = 0; i < 4; i++) {
        float x = tile[tx][ty + i * 8];   // = W[k0+tx][n0+ty+i*8]
        long o = (long)(n0 + ty + i * 8) * D_DIM + k0 + tx;
        __nv_bfloat16 h = __float2bfloat16(x);
        th[o] = h;
        tl[o] = __float2bfloat16(x - __bfloat162float(h));
    }
}

// ---------------------------------------------------------------------------
// Warp-MMA split-precision GEMM: C[M,N] = A @ B^T, A=[M,K] Bt=[N,K] (hi+lo).
// CTA 128x128, 8 warps (2m x 4n), warp tile 64x32, k-tile 32, 2-stage cp.async.
// MODE 0: C row-major [M, 2048]; MODE 1: scatter to [head][m][d].
// ---------------------------------------------------------------------------
template <int MODE>
__global__ __launch_bounds__(256, 1)
void gemm_wmma(const __nv_bfloat16* __restrict__ Ah, const __nv_bfloat16* __restrict__ Al,
               const __nv_bfloat16* __restrict__ Bh, const __nv_bfloat16* __restrict__ Bl,
               float* __restrict__ C)
{
    extern __shared__ __align__(1024) char smem[];
    const uint32_t sb = smem_u32(smem);

    const int t = threadIdx.x, wid = t >> 5, lane = t & 31;
    const int bm = blockIdx.y * 128, bn = blockIdx.x * 128;
    const int wm = wid >> 2, wn = wid & 3;

    const __nv_bfloat16* srcs[4] = {
        Ah + (long)bm * D_DIM, Al + (long)bm * D_DIM,
        Bh + (long)bn * D_DIM, Bl + (long)bn * D_DIM };

    float acc[4][4][4];
#pragma unroll
    for (int i = 0; i < 4; i++)
#pragma unroll
        for (int j = 0; j < 4; j++)
#pragma unroll
            for (int q = 0; q < 4; q++) acc[i][j][q] = 0.0f;

    // ldmatrix lane-address components (constant per thread)
    // A: matrix i = lane>>3 ; m-off = (i&1)*8 ; k-half = (i>>1)*16B
    const int a_row_l = ((lane >> 3) & 1) * 8 + (lane & 7);
    const int a_col_l = ((lane >> 4) & 1) * 16;
    // B: matrix i = lane>>3 ; n-off = (i>>1)*8 ; k-half = (i&1)*16B
    const int b_row_l = ((lane >> 4) & 1) * 8 + (lane & 7);
    const int b_col_l = ((lane >> 3) & 1) * 16;

    const int NKT = D_DIM / 32;   // 64 k-tiles

    // prologue: stage 0
#pragma unroll
    for (int rep = 0; rep < 8; rep++) {
        int idx = t + rep * 256;
        int mat = idx >> 9, row = (idx >> 2) & 127, c = idx & 3;
        cp_async16(sb + mat * 8192 + SWZ64((uint32_t)(row * 64 + c * 16)),
                   srcs[mat] + (long)row * D_DIM + c * 8);
    }
    asm volatile("cp.async.commit_group;" ::: "memory");

    for (int kt = 0; kt < NKT; kt++) {
        const int buf = kt & 1;
        if (kt + 1 < NKT) {
            const int nb = (kt + 1) & 1;
            const int k0 = (kt + 1) * 32;
#pragma unroll
            for (int rep = 0; rep < 8; rep++) {
                int idx = t + rep * 256;
                int mat = idx >> 9, row = (idx >> 2) & 127, c = idx & 3;
                cp_async16(sb + nb * 32768 + mat * 8192 + SWZ64((uint32_t)(row * 64 + c * 16)),
                           srcs[mat] + (long)row * D_DIM + k0 + c * 8);
            }
            asm volatile("cp.async.commit_group;" ::: "memory");
            asm volatile("cp.async.wait_group 1;" ::: "memory");
        } else {
            asm volatile("cp.async.wait_group 0;" ::: "memory");
        }
        __syncthreads();

        const uint32_t base = sb + buf * 32768;
#pragma unroll
        for (int ks = 0; ks < 2; ks++) {
            uint32_t ah[4][4], al[4][4], bh[4][2], bl[4][2];
#pragma unroll
            for (int mt = 0; mt < 4; mt++) {
                int row = wm * 64 + mt * 16 + a_row_l;
                uint32_t off = SWZ64((uint32_t)(row * 64 + ks * 32 + a_col_l));
                ldm_x4(ah[mt][0], ah[mt][1], ah[mt][2], ah[mt][3], base + off);
                ldm_x4(al[mt][0], al[mt][1], al[mt][2], al[mt][3], base + 8192 + off);
            }
#pragma unroll
            for (int g = 0; g < 2; g++) {
                int row = wn * 32 + g * 16 + b_row_l;
                uint32_t off = SWZ64((uint32_t)(row * 64 + ks * 32 + b_col_l));
                uint32_t r0, r1, r2, r3;
                ldm_x4(r0, r1, r2, r3, base + 16384 + off);
                bh[g * 2][0] = r0; bh[g * 2][1] = r1;
                bh[g * 2 + 1][0] = r2; bh[g * 2 + 1][1] = r3;
                ldm_x4(r0, r1, r2, r3, base + 24576 + off);
                bl[g * 2][0] = r0; bl[g * 2][1] = r1;
                bl[g * 2 + 1][0] = r2; bl[g * 2 + 1][1] = r3;
            }
#pragma unroll
            for (int mt = 0; mt < 4; mt++)
#pragma unroll
                for (int nt = 0; nt < 4; nt++) {
                    mma16816(acc[mt][nt], ah[mt], bh[nt]);
                    mma16816(acc[mt][nt], ah[mt], bl[nt]);
                    mma16816(acc[mt][nt], al[mt], bh[nt]);
                }
        }
        __syncthreads();
    }

    // epilogue
#pragma unroll
    for (int mt = 0; mt < 4; mt++) {
#pragma unroll
        for (int nt = 0; nt < 4; nt++) {
            int m0 = bm + wm * 64 + mt * 16 + (lane >> 2);
            int n  = bn + wn * 32 + nt * 8 + (lane & 3) * 2;
#pragma unroll
            for (int hrow = 0; hrow < 2; hrow++) {
                int m = m0 + hrow * 8;
                float2 v = make_float2(acc[mt][nt][hrow * 2], acc[mt][nt][hrow * 2 + 1]);
                if (MODE == 0)
                    *(float2*)(C + (long)m * D_DIM + n) = v;
                else
                    *(float2*)(C + (long)(n >> 7) * (S_LEN * HD) + (long)m * HD + (n & 127)) = v;
            }
        }
    }
}

// ---------------------------------------------------------------------------
// Flash attention (fp32, causal) — unchanged (validated in round 1).
// ---------------------------------------------------------------------------
__global__ __launch_bounds__(256, 1)
void attn_fwd(const float* __restrict__ gq, const float* __restrict__ gk,
              const float* __restrict__ gv, float* __restrict__ gout)
{
    extern __shared__ float sm[];
    float* Qt = sm;                    // [128][65]
    float* Kt = Qt + 128 * 65;         // [128][65]
    float* Vs = Kt + 128 * 65;         // [64][128]
    float* Ss = Vs + 64 * 128;         // [64][65]

    const int qb = blockIdx.x;
    const int h  = blockIdx.y;
    const int t  = threadIdx.x;
    const int tx = t & 15;
    const int ty = t >> 4;
    const int r0 = ty * 4;
    const int c0 = tx * 4;

    const float scale = 0.08838834764831845f;

    const float* qbase = gq + (long)h * S_LEN * HD + (long)qb * 64 * HD;
#pragma unroll
    for (int rep = 0; rep < 32; rep++) {
        int idx = t + rep * 256;
        int row = idx >> 7, d = idx & 127;
        Qt[d * 65 + row] = qbase[idx];
    }

    float mI[4], lI[4], O[4][8];
#pragma unroll
    for (int i = 0; i < 4; i++) {
        mI[i] = -1e30f; lI[i] = 0.0f;
#pragma unroll
        for (int j = 0; j < 8; j++) O[i][j] = 0.0f;
    }

    for (int jb = 0; jb <= qb; jb++) {
        const float* kbase = gk + (long)h * S_LEN * HD + (long)jb * 64 * HD;
        const float* vbase = gv + (long)h * S_LEN * HD + (long)jb * 64 * HD;
#pragma unroll
        for (int rep = 0; rep < 32; rep++) {
            int idx = t + rep * 256;
            int row = idx >> 7, d = idx & 127;
            Kt[d * 65 + row] = kbase[idx];
            Vs[idx]          = vbase[idx];
        }
        __syncthreads();

        float sc[4][4];
#pragma unroll
        for (int i = 0; i < 4; i++)
#pragma unroll
            for (int j = 0; j < 4; j++) sc[i][j] = 0.0f;

#pragma unroll 8
        for (int d = 0; d < 128; d++) {
            float a0 = Qt[d * 65 + r0 + 0];
            float a1 = Qt[d * 65 + r0 + 1];
            float a2 = Qt[d * 65 + r0 + 2];
            float a3 = Qt[d * 65 + r0 + 3];
            float b0 = Kt[d * 65 + c0 + 0];
            float b1 = Kt[d * 65 + c0 + 1];
            float b2 = Kt[d * 65 + c0 + 2];
            float b3 = Kt[d * 65 + c0 + 3];
            sc[0][0] = fmaf(a0, b0, sc[0][0]); sc[0][1] = fmaf(a0, b1, sc[0][1]);
            sc[0][2] = fmaf(a0, b2, sc[0][2]); sc[0][3] = fmaf(a0, b3, sc[0][3]);
            sc[1][0] = fmaf(a1, b0, sc[1][0]); sc[1][1] = fmaf(a1, b1, sc[1][1]);
            sc[1][2] = fmaf(a1, b2, sc[1][2]); sc[1][3] = fmaf(a1, b3, sc[1][3]);
            sc[2][0] = fmaf(a2, b0, sc[2][0]); sc[2][1] = fmaf(a2, b1, sc[2][1]);
            sc[2][2] = fmaf(a2, b2, sc[2][2]); sc[2][3] = fmaf(a2, b3, sc[2][3]);
            sc[3][0] = fmaf(a3, b0, sc[3][0]); sc[3][1] = fmaf(a3, b1, sc[3][1]);
            sc[3][2] = fmaf(a3, b2, sc[3][2]); sc[3][3] = fmaf(a3, b3, sc[3][3]);
        }

        if (jb == qb) {
#pragma unroll
            for (int i = 0; i < 4; i++)
#pragma unroll
                for (int j = 0; j < 4; j++) {
                    float v = sc[i][j] * scale;
                    sc[i][j] = ((c0 + j) > (r0 + i)) ? -1e30f : v;
                }
        } else {
#pragma unroll
            for (int i = 0; i < 4; i++)
#pragma unroll
                for (int j = 0; j < 4; j++) sc[i][j] *= scale;
        }

        float rmax[4];
#pragma unroll
        for (int i = 0; i < 4; i++)
            rmax[i] = fmaxf(fmaxf(sc[i][0], sc[i][1]), fmaxf(sc[i][2], sc[i][3]));
#pragma unroll
        for (int off = 1; off < 16; off <<= 1)
#pragma unroll
            for (int i = 0; i < 4; i++)
                rmax[i] = fmaxf(rmax[i], __shfl_xor_sync(0xffffffffu, rmax[i], off));

        float alpha[4], rsum[4];
#pragma unroll
        for (int i = 0; i < 4; i++) {
            float nm = fmaxf(mI[i], rmax[i]);
            alpha[i] = __expf(mI[i] - nm);
            mI[i] = nm;
            float s = 0.0f;
#pragma unroll
            for (int j = 0; j < 4; j++) {
                float p = __expf(sc[i][j] - nm);
                Ss[(r0 + i) * 65 + c0 + j] = p;
                s += p;
            }
            rsum[i] = s;
        }
#pragma unroll
        for (int off = 1; off < 16; off <<= 1)
#pragma unroll
            for (int i = 0; i < 4; i++)
                rsum[i] += __shfl_xor_sync(0xffffffffu, rsum[i], off);
#pragma unroll
        for (int i = 0; i < 4; i++) {
            lI[i] = lI[i] * alpha[i] + rsum[i];
#pragma unroll
            for (int j = 0; j < 8; j++) O[i][j] *= alpha[i];
        }
        __syncthreads();

#pragma unroll 4
        for (int kk = 0; kk < 64; kk++) {
            float sv0 = Ss[(r0 + 0) * 65 + kk];
            float sv1 = Ss[(r0 + 1) * 65 + kk];
            float sv2 = Ss[(r0 + 2) * 65 + kk];
            float sv3 = Ss[(r0 + 3) * 65 + kk];
            float vv[8];
#pragma unroll
            for (int j = 0; j < 8; j++) vv[j] = Vs[kk * 128 + tx + 16 * j];
#pragma unroll
            for (int j = 0; j < 8; j++) {
                O[0][j] = fmaf(sv0, vv[j], O[0][j]);
                O[1][j] = fmaf(sv1, vv[j], O[1][j]);
                O[2][j] = fmaf(sv2, vv[j], O[2][j]);
                O[3][j] = fmaf(sv3, vv[j], O[3][j]);
            }
        }
        __syncthreads();
    }

#pragma unroll
    for (int i = 0; i < 4; i++) {
        float inv = 1.0f / lI[i];
        int srow = qb * 64 + r0 + i;
#pragma unroll
        for (int j = 0; j < 8; j++) {
            gout[(long)srow * D_DIM + h * HD + tx + 16 * j] = O[i][j] * inv;
        }
    }
}

// ---------------------------------------------------------------------------
extern "C" void kernel_launch(void* const* d_in, const int* in_sizes, int n_in,
                              void* d_out, int out_size)
{
    const float* hs = (const float*)d_in[0];
    const float* Wq = (const float*)d_in[1];
    const float* Wk = (const float*)d_in[2];
    const float* Wv = (const float*)d_in[3];
    const float* Wo = (const float*)d_in[4];
    float* out = (float*)d_out;

    float *q, *k, *v, *att;
    cudaGetSymbolAddress((void**)&q,   g_q);
    cudaGetSymbolAddress((void**)&k,   g_k);
    cudaGetSymbolAddress((void**)&v,   g_v);
    cudaGetSymbolAddress((void**)&att, g_att);

    __nv_bfloat16 *hsh, *hsl, *wh, *wl, *atth, *attl;
    cudaGetSymbolAddress((void**)&hsh,  g_hs_h);
    cudaGetSymbolAddress((void**)&hsl,  g_hs_l);
    cudaGetSymbolAddress((void**)&wh,   g_w_h);
    cudaGetSymbolAddress((void**)&wl,   g_w_l);
    cudaGetSymbolAddress((void**)&atth, g_att_h);
    cudaGetSymbolAddress((void**)&attl, g_att_l);

    const int WSZ = D_DIM * D_DIM;
    const int n2  = S_LEN * D_DIM / 2;

    split_kernel<<<2048, 256>>>(hs, hsh, hsl, n2);
    dim3 tg(D_DIM / 32, D_DIM / 32), tb(32, 8);
    splitT_kernel<<<tg, tb>>>(Wq, wh + 0 * WSZ, wl + 0 * WSZ);
    splitT_kernel<<<tg, tb>>>(Wk, wh + 1 * WSZ, wl + 1 * WSZ);
    splitT_kernel<<<tg, tb>>>(Wv, wh + 2 * WSZ, wl + 2 * WSZ);
    splitT_kernel<<<tg, tb>>>(Wo, wh + 3 * WSZ, wl + 3 * WSZ);

    const int gsmem = 65536;
    cudaFuncSetAttribute(gemm_wmma<0>, cudaFuncAttributeMaxDynamicSharedMemorySize, gsmem);
    cudaFuncSetAttribute(gemm_wmma<1>, cudaFuncAttributeMaxDynamicSharedMemorySize, gsmem);
    dim3 gg(D_DIM / 128, S_LEN / 128);   // (16, 32)

    gemm_wmma<1><<<gg, 256, gsmem>>>(hsh, hsl, wh + 0 * WSZ, wl + 0 * WSZ, q);
    gemm_wmma<1><<<gg, 256, gsmem>>>(hsh, hsl, wh + 1 * WSZ, wl + 1 * WSZ, k);
    gemm_wmma<1><<<gg, 256, gsmem>>>(hsh, hsl, wh + 2 * WSZ, wl + 2 * WSZ, v);

    const int asmem = (128 * 65 * 2 + 64 * 128 + 64 * 65) * (int)sizeof(float);
    cudaFuncSetAttribute(attn_fwd, cudaFuncAttributeMaxDynamicSharedMemorySize, asmem);
    attn_fwd<<<dim3(S_LEN / 64, NHEAD), 256, asmem>>>(q, k, v, att);

    split_kernel<<<2048, 256>>>(att, atth, attl, n2);
    gemm_wmma<0><<<gg, 256, gsmem>>>(atth, attl, wh + 3 * WSZ, wl + 3 * WSZ, out);
}

// round 4
// speedup vs baseline: 3.1933x; 2.0006x over previous
#include <cuda_runtime.h>
#include <cuda_bf16.h>
#include <math.h>
#include <cstdint>

#define S_LEN 4096
#define D_DIM 2048
#define NHEAD 16
#define HD    128

// ---------------- scratch (allocation-free) ----------------
__device__ __nv_bfloat16 g_hs_h[S_LEN * D_DIM];
__device__ __nv_bfloat16 g_hs_l[S_LEN * D_DIM];
__device__ __nv_bfloat16 g_w_h[4][D_DIM * D_DIM];   // transposed: [N][K]
__device__ __nv_bfloat16 g_w_l[4][D_DIM * D_DIM];
__device__ __nv_bfloat16 g_qh[NHEAD * S_LEN * HD];
__device__ __nv_bfloat16 g_ql[NHEAD * S_LEN * HD];
__device__ __nv_bfloat16 g_kh[NHEAD * S_LEN * HD];
__device__ __nv_bfloat16 g_kl[NHEAD * S_LEN * HD];
__device__ __nv_bfloat16 g_vh[NHEAD * S_LEN * HD];
__device__ __nv_bfloat16 g_vl[NHEAD * S_LEN * HD];
__device__ __nv_bfloat16 g_att_h[S_LEN * D_DIM];
__device__ __nv_bfloat16 g_att_l[S_LEN * D_DIM];

// ---------------- helpers ----------------
__device__ __forceinline__ uint32_t smem_u32(const void* p) {
    uint32_t a;
    asm("{ .reg .u64 t; cvta.to.shared.u64 t, %1; cvt.u32.u64 %0, t; }" : "=r"(a) : "l"(p));
    return a;
}

__device__ __forceinline__ void ldm_x4(uint32_t& r0, uint32_t& r1, uint32_t& r2, uint32_t& r3,
                                       uint32_t addr) {
    asm volatile("ldmatrix.sync.aligned.m8n8.x4.shared.b16 {%0,%1,%2,%3}, [%4];"
                 : "=r"(r0), "=r"(r1), "=r"(r2), "=r"(r3) : "r"(addr));
}

__device__ __forceinline__ void ldm_x4t(uint32_t& r0, uint32_t& r1, uint32_t& r2, uint32_t& r3,
                                        uint32_t addr) {
    asm volatile("ldmatrix.sync.aligned.m8n8.x4.trans.shared.b16 {%0,%1,%2,%3}, [%4];"
                 : "=r"(r0), "=r"(r1), "=r"(r2), "=r"(r3) : "r"(addr));
}

__device__ __forceinline__ void mma16816(float* c, const uint32_t* a, const uint32_t* b) {
    asm volatile(
        "mma.sync.aligned.m16n8k16.row.col.f32.bf16.bf16.f32 "
        "{%0,%1,%2,%3}, {%4,%5,%6,%7}, {%8,%9}, {%0,%1,%2,%3};"
        : "+f"(c[0]), "+f"(c[1]), "+f"(c[2]), "+f"(c[3])
        : "r"(a[0]), "r"(a[1]), "r"(a[2]), "r"(a[3]), "r"(b[0]), "r"(b[1]));
}

__device__ __forceinline__ void cp_async16(uint32_t s, const void* g) {
    asm volatile("cp.async.cg.shared.global [%0], [%1], 16;" :: "r"(s), "l"(g));
}

__device__ __forceinline__ uint32_t pack_bf16x2(float lo, float hi) {
    uint32_t r;
    asm("cvt.rn.bf16x2.f32 %0, %1, %2;" : "=r"(r) : "f"(hi), "f"(lo));
    return r;
}

__device__ __forceinline__ float bf16_err(float x) {
    return x - __bfloat162float(__float2bfloat16(x));
}

#define SWZ64(o) ((o) ^ (((o) >> 3) & 0x30))
// 256B rows: XOR 16B-chunk index with low 3 bits of row
#define SWZ256(row, chunk) ((uint32_t)((row) * 256 + ((((chunk) ^ ((row) & 7))) << 4)))

// ---------------------------------------------------------------------------
// split helpers for inputs
// ---------------------------------------------------------------------------
__global__ void split_kernel(const float* __restrict__ in,
                             __nv_bfloat16* __restrict__ hi,
                             __nv_bfloat16* __restrict__ lo, int n2)
{
    int i = blockIdx.x * blockDim.x + threadIdx.x;
    int stride = gridDim.x * blockDim.x;
    for (; i < n2; i += stride) {
        float2 x = ((const float2*)in)[i];
        __nv_bfloat16 h0 = __float2bfloat16(x.x);
        __nv_bfloat16 h1 = __float2bfloat16(x.y);
        __nv_bfloat16 l0 = __float2bfloat16(x.x - __bfloat162float(h0));
        __nv_bfloat16 l1 = __float2bfloat16(x.y - __bfloat162float(h1));
        ((__nv_bfloat162*)hi)[i] = __nv_bfloat162(h0, h1);
        ((__nv_bfloat162*)lo)[i] = __nv_bfloat162(l0, l1);
    }
}

__global__ void splitT_kernel(const float* __restrict__ W,
                              __nv_bfloat16* __restrict__ th,
                              __nv_bfloat16* __restrict__ tl)
{
    __shared__ float tile[32][33];
    const int n0 = blockIdx.x * 32;
    const int k0 = blockIdx.y * 32;
    const int tx = threadIdx.x, ty = threadIdx.y;
#pragma unroll
    for (int i = 0; i < 4; i++)
        tile[ty + i * 8][tx] = W[(long)(k0 + ty + i * 8) * D_DIM + n0 + tx];
    __syncthreads();
#pragma unroll
    for (int i = 0; i < 4; i++) {
        float x = tile[tx][ty + i * 8];
        long o = (long)(n0 + ty + i * 8) * D_DIM + k0 + tx;
        __nv_bfloat16 h = __float2bfloat16(x);
        th[o] = h;
        tl[o] = __float2bfloat16(x - __bfloat162float(h));
    }
}

// ---------------------------------------------------------------------------
// Split-precision warp-MMA GEMM (validated round 3).
// MODE 0: fp32 C row-major [M, 2048].
// MODE 1: bf16 hi/lo outputs scattered to [head][m][d], values scaled.
// ---------------------------------------------------------------------------
template <int MODE>
__global__ __launch_bounds__(256, 1)
void gemm_wmma(const __nv_bfloat16* __restrict__ Ah, const __nv_bfloat16* __restrict__ Al,
               const __nv_bfloat16* __restrict__ Bh, const __nv_bfloat16* __restrict__ Bl,
               float* __restrict__ C,
               __nv_bfloat16* __restrict__ Oh, __nv_bfloat16* __restrict__ Ol,
               float scale)
{
    extern __shared__ __align__(1024) char smem[];
    const uint32_t sb = smem_u32(smem);

    const int t = threadIdx.x, wid = t >> 5, lane = t & 31;
    const int bm = blockIdx.y * 128, bn = blockIdx.x * 128;
    const int wm = wid >> 2, wn = wid & 3;

    const __nv_bfloat16* srcs[4] = {
        Ah + (long)bm * D_DIM, Al + (long)bm * D_DIM,
        Bh + (long)bn * D_DIM, Bl + (long)bn * D_DIM };

    float acc[4][4][4];
#pragma unroll
    for (int i = 0; i < 4; i++)
#pragma unroll
        for (int j = 0; j < 4; j++)
#pragma unroll
            for (int q = 0; q < 4; q++) acc[i][j][q] = 0.0f;

    const int a_row_l = ((lane >> 3) & 1) * 8 + (lane & 7);
    const int a_col_l = ((lane >> 4) & 1) * 16;
    const int b_row_l = ((lane >> 4) & 1) * 8 + (lane & 7);
    const int b_col_l = ((lane >> 3) & 1) * 16;

    const int NKT = D_DIM / 32;

#pragma unroll
    for (int rep = 0; rep < 8; rep++) {
        int idx = t + rep * 256;
        int mat = idx >> 9, row = (idx >> 2) & 127, c = idx & 3;
        cp_async16(sb + mat * 8192 + SWZ64((uint32_t)(row * 64 + c * 16)),
                   srcs[mat] + (long)row * D_DIM + c * 8);
    }
    asm volatile("cp.async.commit_group;" ::: "memory");

    for (int kt = 0; kt < NKT; kt++) {
        const int buf = kt & 1;
        if (kt + 1 < NKT) {
            const int nb = (kt + 1) & 1;
            const int k0 = (kt + 1) * 32;
#pragma unroll
            for (int rep = 0; rep < 8; rep++) {
                int idx = t + rep * 256;
                int mat = idx >> 9, row = (idx >> 2) & 127, c = idx & 3;
                cp_async16(sb + nb * 32768 + mat * 8192 + SWZ64((uint32_t)(row * 64 + c * 16)),
                           srcs[mat] + (long)row * D_DIM + k0 + c * 8);
            }
            asm volatile("cp.async.commit_group;" ::: "memory");
            asm volatile("cp.async.wait_group 1;" ::: "memory");
        } else {
            asm volatile("cp.async.wait_group 0;" ::: "memory");
        }
        __syncthreads();

        const uint32_t base = sb + buf * 32768;
#pragma unroll
        for (int ks = 0; ks < 2; ks++) {
            uint32_t ah[4][4], al[4][4], bh[4][2], bl[4][2];
#pragma unroll
            for (int mt = 0; mt < 4; mt++) {
                int row = wm * 64 + mt * 16 + a_row_l;
                uint32_t off = SWZ64((uint32_t)(row * 64 + ks * 32 + a_col_l));
                ldm_x4(ah[mt][0], ah[mt][1], ah[mt][2], ah[mt][3], base + off);
                ldm_x4(al[mt][0], al[mt][1], al[mt][2], al[mt][3], base + 8192 + off);
            }
#pragma unroll
            for (int g = 0; g < 2; g++) {
                int row = wn * 32 + g * 16 + b_row_l;
                uint32_t off = SWZ64((uint32_t)(row * 64 + ks * 32 + b_col_l));
                uint32_t r0, r1, r2, r3;
                ldm_x4(r0, r1, r2, r3, base + 16384 + off);
                bh[g * 2][0] = r0; bh[g * 2][1] = r1;
                bh[g * 2 + 1][0] = r2; bh[g * 2 + 1][1] = r3;
                ldm_x4(r0, r1, r2, r3, base + 24576 + off);
                bl[g * 2][0] = r0; bl[g * 2][1] = r1;
                bl[g * 2 + 1][0] = r2; bl[g * 2 + 1][1] = r3;
            }
#pragma unroll
            for (int mt = 0; mt < 4; mt++)
#pragma unroll
                for (int nt = 0; nt < 4; nt++) {
                    mma16816(acc[mt][nt], ah[mt], bh[nt]);
                    mma16816(acc[mt][nt], ah[mt], bl[nt]);
                    mma16816(acc[mt][nt], al[mt], bh[nt]);
                }
        }
        __syncthreads();
    }

#pragma unroll
    for (int mt = 0; mt < 4; mt++) {
#pragma unroll
        for (int nt = 0; nt < 4; nt++) {
            int m0 = bm + wm * 64 + mt * 16 + (lane >> 2);
            int n  = bn + wn * 32 + nt * 8 + (lane & 3) * 2;
#pragma unroll
            for (int hrow = 0; hrow < 2; hrow++) {
                int m = m0 + hrow * 8;
                float x0 = acc[mt][nt][hrow * 2], x1 = acc[mt][nt][hrow * 2 + 1];
                if (MODE == 0) {
                    *(float2*)(C + (long)m * D_DIM + n) = make_float2(x0, x1);
                } else {
                    x0 *= scale; x1 *= scale;
                    long o = ((long)(n >> 7) * S_LEN + m) * HD + (n & 127);
                    float h0 = __bfloat162float(__float2bfloat16(x0));
                    float h1 = __bfloat162float(__float2bfloat16(x1));
                    *(uint32_t*)(Oh + o) = pack_bf16x2(h0, h1);
                    *(uint32_t*)(Ol + o) = pack_bf16x2(x0 - h0, x1 - h1);
                }
            }
        }
    }
}

// ---------------------------------------------------------------------------
// Tensor-core flash attention (bf16 split, causal).
// CTA: 128 q-rows x 1 head. 8 warps, 16 rows each. KV tiles of 64 rows.
// 3-stage cp.async ring, 64KB/stage (Kh,Kl,Vh,Vl each 16KB, [64][256B] SWZ256).
// Q pre-scaled by 1/sqrt(128)*log2(e); softmax in exp2 domain.
// Output written as bf16 hi/lo split to [S][D].
// ---------------------------------------------------------------------------
__global__ __launch_bounds__(256, 1)
void attn_tc(const __nv_bfloat16* __restrict__ qh, const __nv_bfloat16* __restrict__ ql,
             const __nv_bfloat16* __restrict__ kh, const __nv_bfloat16* __restrict__ kl,
             const __nv_bfloat16* __restrict__ vh, const __nv_bfloat16* __restrict__ vl,
             __nv_bfloat16* __restrict__ oh, __nv_bfloat16* __restrict__ ol)
{
    extern __shared__ __align__(1024) char smem[];
    const uint32_t sb = smem_u32(smem);

    const int t = threadIdx.x, w = t >> 5, lane = t & 31;
    const int h = blockIdx.y;
    const int qb = gridDim.x - 1 - blockIdx.x;     // largest-work first
    const long hoff = (long)h * S_LEN * HD;
    const int jbmax = 2 * qb + 1;

    const __nv_bfloat16* kvsrc[4] = { kh + hoff, kl + hoff, vh + hoff, vl + hoff };

    // ---- prologue: Q -> stage0 region, KV0 -> stage1, KV1 -> stage2 ----
    {
        const __nv_bfloat16* q0h = qh + hoff + (long)qb * 128 * HD;
        const __nv_bfloat16* q0l = ql + hoff + (long)qb * 128 * HD;
#pragma unroll
        for (int rep = 0; rep < 8; rep++) {
            int i = t + rep * 256;
            int row = i >> 4, c = i & 15;
            cp_async16(sb + SWZ256(row, c), q0h + (long)row * HD + c * 8);
            cp_async16(sb + 32768 + SWZ256(row, c), q0l + (long)row * HD + c * 8);
        }
        asm volatile("cp.async.commit_group;" ::: "memory");
    }
#pragma unroll
    for (int pj = 0; pj < 2; pj++) {
        uint32_t dst = sb + (pj + 1) * 65536;
#pragma unroll
        for (int m = 0; m < 4; m++) {
            const __nv_bfloat16* src = kvsrc[m] + (long)pj * 64 * HD;
#pragma unroll
            for (int rep = 0; rep < 4; rep++) {
                int i = t + rep * 256;
                int row = i >> 4, c = i & 15;
                cp_async16(dst + m * 16384 + SWZ256(row, c), src + (long)row * HD + c * 8);
            }
        }
        asm volatile("cp.async.commit_group;" ::: "memory");
    }

    asm volatile("cp.async.wait_group 2;" ::: "memory");
    __syncthreads();

    // ---- read Q fragments to registers ----
    uint32_t qfh[8][4], qfl[8][4];
    {
        int row = w * 16 + (lane & 15);
        int csel = (lane >> 4) & 1;
#pragma unroll
        for (int kc = 0; kc < 8; kc++) {
            uint32_t off = SWZ256(row, kc * 2 + csel);
            ldm_x4(qfh[kc][0], qfh[kc][1], qfh[kc][2], qfh[kc][3], sb + off);
            ldm_x4(qfl[kc][0], qfl[kc][1], qfl[kc][2], qfl[kc][3], sb + 32768 + off);
        }
    }
    __syncthreads();   // stage0 now free for the ring

    float O[16][4];
#pragma unroll
    for (int i = 0; i < 16; i++)
#pragma unroll
        for (int j = 0; j < 4; j++) O[i][j] = 0.0f;
    float m0 = -1e30f, m1 = -1e30f, l0 = 0.0f, l1 = 0.0f;

    const int b_row_l = ((lane >> 4) & 1) * 8 + (lane & 7);
    const int b_csel  = (lane >> 3) & 1;
    const int vt_row_l = ((lane >> 3) & 1) * 8 + (lane & 7);
    const int vt_csel  = (lane >> 4) & 1;
    const int q0row = qb * 128 + w * 16 + (lane >> 2);

    for (int jb = 0; jb <= jbmax; jb++) {
        if (jb < jbmax) { asm volatile("cp.async.wait_group 1;" ::: "memory"); }
        else            { asm volatile("cp.async.wait_group 0;" ::: "memory"); }
        __syncthreads();

        const uint32_t stage = sb + (uint32_t)(((jb + 1) % 3) * 65536);

        // ---- S = Q K^T ----
        float S[8][4];
#pragma unroll
        for (int i = 0; i < 8; i++)
#pragma unroll
            for (int j = 0; j < 4; j++) S[i][j] = 0.0f;

#pragma unroll
        for (int kc = 0; kc < 8; kc++) {
#pragma unroll
            for (int np = 0; np < 4; np++) {
                int row = np * 16 + b_row_l;
                uint32_t off = SWZ256(row, kc * 2 + b_csel);
                uint32_t h0, h1, h2, h3, e0, e1, e2, e3;
                ldm_x4(h0, h1, h2, h3, stage + off);
                ldm_x4(e0, e1, e2, e3, stage + 16384 + off);
                uint32_t bh0[2] = {h0, h1}, bh1[2] = {h2, h3};
                uint32_t bl0[2] = {e0, e1}, bl1[2] = {e2, e3};
                mma16816(S[2 * np],     qfh[kc], bh0);
                mma16816(S[2 * np],     qfh[kc], bl0);
                mma16816(S[2 * np],     qfl[kc], bh0);
                mma16816(S[2 * np + 1], qfh[kc], bh1);
                mma16816(S[2 * np + 1], qfh[kc], bl1);
                mma16816(S[2 * np + 1], qfl[kc], bh1);
            }
        }

        // ---- causal mask (only for the top two diagonal tiles) ----
        if (jb >= 2 * qb) {
            int kvb = jb * 64 + 2 * (lane & 3);
#pragma unroll
            for (int nt = 0; nt < 8; nt++) {
                int kv = kvb + nt * 8;
                if (kv     > q0row)     S[nt][0] = -1e30f;
                if (kv + 1 > q0row)     S[nt][1] = -1e30f;
                if (kv     > q0row + 8) S[nt][2] = -1e30f;
                if (kv + 1 > q0row + 8) S[nt][3] = -1e30f;
            }
        }

        // ---- online softmax (exp2 domain) ----
        float mx0 = -1e30f, mx1 = -1e30f;
#pragma unroll
        for (int nt = 0; nt < 8; nt++) {
            mx0 = fmaxf(mx0, fmaxf(S[nt][0], S[nt][1]));
            mx1 = fmaxf(mx1, fmaxf(S[nt][2], S[nt][3]));
        }
        mx0 = fmaxf(mx0, __shfl_xor_sync(0xffffffffu, mx0, 1));
        mx0 = fmaxf(mx0, __shfl_xor_sync(0xffffffffu, mx0, 2));
        mx1 = fmaxf(mx1, __shfl_xor_sync(0xffffffffu, mx1, 1));
        mx1 = fmaxf(mx1, __shfl_xor_sync(0xffffffffu, mx1, 2));

        float nm0 = fmaxf(m0, mx0), nm1 = fmaxf(m1, mx1);
        float al0 = exp2f(m0 - nm0), al1 = exp2f(m1 - nm1);
        m0 = nm0; m1 = nm1;

        float s0 = 0.0f, s1 = 0.0f;
#pragma unroll
        for (int nt = 0; nt < 8; nt++) {
            S[nt][0] = exp2f(S[nt][0] - nm0); s0 += S[nt][0];
            S[nt][1] = exp2f(S[nt][1] - nm0); s0 += S[nt][1];
            S[nt][2] = exp2f(S[nt][2] - nm1); s1 += S[nt][2];
            S[nt][3] = exp2f(S[nt][3] - nm1); s1 += S[nt][3];
        }
        s0 += __shfl_xor_sync(0xffffffffu, s0, 1);
        s0 += __shfl_xor_sync(0xffffffffu, s0, 2);
        s1 += __shfl_xor_sync(0xffffffffu, s1, 1);
        s1 += __shfl_xor_sync(0xffffffffu, s1, 2);
        l0 = l0 * al0 + s0;
        l1 = l1 * al1 + s1;

#pragma unroll
        for (int nt = 0; nt < 16; nt++) {
            O[nt][0] *= al0; O[nt][1] *= al0;
            O[nt][2] *= al1; O[nt][3] *= al1;
        }

        // ---- O += P V : P acc regs -> A fragments in-register ----
#pragma unroll
        for (int kc = 0; kc < 4; kc++) {
            float p00 = S[2 * kc][0],     p01 = S[2 * kc][1];
            float p02 = S[2 * kc][2],     p03 = S[2 * kc][3];
            float p10 = S[2 * kc + 1][0], p11 = S[2 * kc + 1][1];
            float p12 = S[2 * kc + 1][2], p13 = S[2 * kc + 1][3];
            float h00 = __bfloat162float(__float2bfloat16(p00));
            float h01 = __bfloat162float(__float2bfloat16(p01));
            float h02 = __bfloat162float(__float2bfloat16(p02));
            float h03 = __bfloat162float(__float2bfloat16(p03));
            float h10 = __bfloat162float(__float2bfloat16(p10));
            float h11 = __bfloat162float(__float2bfloat16(p11));
            float h12 = __bfloat162float(__float2bfloat16(p12));
            float h13 = __bfloat162float(__float2bfloat16(p13));
            uint32_t ah[4], al[4];
            ah[0] = pack_bf16x2(h00, h01); ah[1] = pack_bf16x2(h02, h03);
            ah[2] = pack_bf16x2(h10, h11); ah[3] = pack_bf16x2(h12, h13);
            al[0] = pack_bf16x2(p00 - h00, p01 - h01);
            al[1] = pack_bf16x2(p02 - h02, p03 - h03);
            al[2] = pack_bf16x2(p10 - h10, p11 - h11);
            al[3] = pack_bf16x2(p12 - h12, p13 - h13);

            int vrow = kc * 16 + vt_row_l;
#pragma unroll
            for (int np = 0; np < 8; np++) {
                uint32_t off = SWZ256(vrow, np * 2 + vt_csel);
                uint32_t r0, r1, r2, r3, u0, u1, u2, u3;
                ldm_x4t(r0, r1, r2, r3, stage + 32768 + off);
                ldm_x4t(u0, u1, u2, u3, stage + 49152 + off);
                uint32_t vh0[2] = {r0, r1}, vh1[2] = {r2, r3};
                uint32_t vl0[2] = {u0, u1}, vl1[2] = {u2, u3};
                mma16816(O[2 * np],     ah, vh0);
                mma16816(O[2 * np],     ah, vl0);
                mma16816(O[2 * np],     al, vh0);
                mma16816(O[2 * np + 1], ah, vh1);
                mma16816(O[2 * np + 1], ah, vl1);
                mma16816(O[2 * np + 1], al, vh1);
            }
        }

        // ---- prefetch KV(jb+2) into the stage freed two iterations ago ----
        if (jb + 2 <= jbmax) {
            uint32_t dst = sb + (uint32_t)(((jb + 3) % 3) * 65536);
#pragma unroll
            for (int m = 0; m < 4; m++) {
                const __nv_bfloat16* src = kvsrc[m] + (long)(jb + 2) * 64 * HD;
#pragma unroll
                for (int rep = 0; rep < 4; rep++) {
                    int i = t + rep * 256;
                    int row = i >> 4, c = i & 15;
                    cp_async16(dst + m * 16384 + SWZ256(row, c), src + (long)row * HD + c * 8);
                }
            }
            asm volatile("cp.async.commit_group;" ::: "memory");
        }
    }

    // ---- epilogue: normalize, write bf16 hi/lo att in [S][D] ----
    float inv0 = 1.0f / l0, inv1 = 1.0f / l1;
    int row0 = qb * 128 + w * 16 + (lane >> 2);
    int colb = h * HD + 2 * (lane & 3);
#pragma unroll
    for (int nt = 0; nt < 16; nt++) {
        int d = nt * 8;
        long o0 = (long)row0 * D_DIM + colb + d;
        long o1 = (long)(row0 + 8) * D_DIM + colb + d;
        float x0 = O[nt][0] * inv0, x1 = O[nt][1] * inv0;
        float y0 = O[nt][2] * inv1, y1 = O[nt][3] * inv1;
        float hx0 = __bfloat162float(__float2bfloat16(x0));
        float hx1 = __bfloat162float(__float2bfloat16(x1));
        float hy0 = __bfloat162float(__float2bfloat16(y0));
        float hy1 = __bfloat162float(__float2bfloat16(y1));
        *(uint32_t*)(oh + o0) = pack_bf16x2(hx0, hx1);
        *(uint32_t*)(ol + o0) = pack_bf16x2(x0 - hx0, x1 - hx1);
        *(uint32_t*)(oh + o1) = pack_bf16x2(hy0, hy1);
        *(uint32_t*)(ol + o1) = pack_bf16x2(y0 - hy0, y1 - hy1);
    }
}

// ---------------------------------------------------------------------------
extern "C" void kernel_launch(void* const* d_in, const int* in_sizes, int n_in,
                              void* d_out, int out_size)
{
    const float* hs = (const float*)d_in[0];
    const float* Wq = (const float*)d_in[1];
    const float* Wk = (const float*)d_in[2];
    const float* Wv = (const float*)d_in[3];
    const float* Wo = (const float*)d_in[4];
    float* out = (float*)d_out;

    __nv_bfloat16 *hsh, *hsl, *wh, *wl, *atth, *attl;
    __nv_bfloat16 *pqh, *pql, *pkh, *pkl, *pvh, *pvl;
    cudaGetSymbolAddress((void**)&hsh,  g_hs_h);
    cudaGetSymbolAddress((void**)&hsl,  g_hs_l);
    cudaGetSymbolAddress((void**)&wh,   g_w_h);
    cudaGetSymbolAddress((void**)&wl,   g_w_l);
    cudaGetSymbolAddress((void**)&atth, g_att_h);
    cudaGetSymbolAddress((void**)&attl, g_att_l);
    cudaGetSymbolAddress((void**)&pqh,  g_qh);
    cudaGetSymbolAddress((void**)&pql,  g_ql);
    cudaGetSymbolAddress((void**)&pkh,  g_kh);
    cudaGetSymbolAddress((void**)&pkl,  g_kl);
    cudaGetSymbolAddress((void**)&pvh,  g_vh);
    cudaGetSymbolAddress((void**)&pvl,  g_vl);

    const int WSZ = D_DIM * D_DIM;
    const int n2  = S_LEN * D_DIM / 2;

    split_kernel<<<2048, 256>>>(hs, hsh, hsl, n2);
    dim3 tg(D_DIM / 32, D_DIM / 32), tb(32, 8);
    splitT_kernel<<<tg, tb>>>(Wq, wh + 0 * WSZ, wl + 0 * WSZ);
    splitT_kernel<<<tg, tb>>>(Wk, wh + 1 * WSZ, wl + 1 * WSZ);
    splitT_kernel<<<tg, tb>>>(Wv, wh + 2 * WSZ, wl + 2 * WSZ);
    splitT_kernel<<<tg, tb>>>(Wo, wh + 3 * WSZ, wl + 3 * WSZ);

    const int gsmem = 65536;
    cudaFuncSetAttribute(gemm_wmma<0>, cudaFuncAttributeMaxDynamicSharedMemorySize, gsmem);
    cudaFuncSetAttribute(gemm_wmma<1>, cudaFuncAttributeMaxDynamicSharedMemorySize, gsmem);
    dim3 gg(D_DIM / 128, S_LEN / 128);

    const float qscale = 0.08838834764831845f * 1.4426950408889634f;  // 1/sqrt(128)*log2(e)
    gemm_wmma<1><<<gg, 256, gsmem>>>(hsh, hsl, wh + 0 * WSZ, wl + 0 * WSZ,
                                     nullptr, pqh, pql, qscale);
    gemm_wmma<1><<<gg, 256, gsmem>>>(hsh, hsl, wh + 1 * WSZ, wl + 1 * WSZ,
                                     nullptr, pkh, pkl, 1.0f);
    gemm_wmma<1><<<gg, 256, gsmem>>>(hsh, hsl, wh + 2 * WSZ, wl + 2 * WSZ,
                                     nullptr, pvh, pvl, 1.0f);

    const int asmem = 3 * 65536;
    cudaFuncSetAttribute(attn_tc, cudaFuncAttributeMaxDynamicSharedMemorySize, asmem);
    attn_tc<<<dim3(S_LEN / 128, NHEAD), 256, asmem>>>(pqh, pql, pkh, pkl, pvh, pvl,
                                                      atth, attl);

    gemm_wmma<0><<<gg, 256, gsmem>>>(atth, attl, wh + 3 * WSZ, wl + 3 * WSZ,
                                     out, nullptr, nullptr, 1.0f);
}